// round 6
// baseline (speedup 1.0000x reference)
#include <cuda_runtime.h>
#include <math.h>

// Problem constants
#define BB  4
#define TT  1024
#define DD  768
#define NCH 7
#define BT  (BB*TT)   // 4096 rows

// ---------------------------------------------------------------------------
// Scratch (device globals; no allocation allowed in kernel_launch)
// ---------------------------------------------------------------------------
__device__ float g_h    [(size_t)BT*DD];
__device__ float g_in   [(size_t)BT*DD];
__device__ float g_q    [(size_t)BT*DD];
__device__ float g_k    [(size_t)BT*DD];
__device__ float g_o    [(size_t)BT*DD];
__device__ float g_seq  [(size_t)BT*DD];
__device__ float g_delta[(size_t)BT*DD];
__device__ float g_par  [(size_t)BT*DD];
__device__ float g_S    [(size_t)BB*TT*TT];   // 16.8 MB attention scores / probs

// ---------------------------------------------------------------------------
// SGEMM: C = alpha * A @ op(B) (+ C if ACC)
//   A: M x K, row-major, leading dim lda
//   B: if TRANSB: N x K row-major (B[n*ldb + k]); else K x N (B[k*ldb + n])
//   batched over blockIdx.z with element strides sA/sB/sC
//   CSKIP: skip C tiles entirely above the diagonal (for causal QK^T)
//   CKLIM: A[m,k]==0 for k>m -> cap K loop at tile diagonal (for P@V)
// Tiles: 128x128x8, 256 threads, 8x8 per thread. All dims assumed %128==0,
// K %8==0 (true for all launches here).
// ---------------------------------------------------------------------------
template<bool TRANSB, bool ACC, bool CSKIP, bool CKLIM>
__global__ void __launch_bounds__(256)
sgemm_kernel(const float* __restrict__ A, int lda, long long sA,
             const float* __restrict__ Bp, int ldb, long long sB,
             float* __restrict__ C, int ldc, long long sC,
             int M, int N, int K, float alpha)
{
    const int BM = 128, BN = 128, BK = 8;
    __shared__ float As[BK][BM];
    __shared__ float Bs[BK][BN];

    const int m0 = blockIdx.y * BM;
    const int n0 = blockIdx.x * BN;
    if (CSKIP && n0 > m0 + BM - 1) return;   // tile fully above diagonal: never read

    const int z = blockIdx.z;
    A  += (long long)z * sA;
    Bp += (long long)z * sB;
    C  += (long long)z * sC;

    int kend = K;
    if (CKLIM) { int ke = m0 + BM; kend = (ke < K) ? ke : K; }

    const int tid = threadIdx.x;
    const int tx  = tid & 15;     // 0..15 (n)
    const int ty  = tid >> 4;     // 0..15 (m)

    // global->shared load indices
    const int arow = tid >> 1;            // 0..127
    const int acol = (tid & 1) * 4;       // 0 or 4

    float acc[8][8];
    #pragma unroll
    for (int i = 0; i < 8; i++)
        #pragma unroll
        for (int j = 0; j < 8; j++) acc[i][j] = 0.f;

    for (int k0 = 0; k0 < kend; k0 += BK) {
        // A tile: 128 x 8, store transposed
        float4 av = *reinterpret_cast<const float4*>(
            &A[(long long)(m0 + arow) * lda + k0 + acol]);
        As[acol + 0][arow] = av.x;
        As[acol + 1][arow] = av.y;
        As[acol + 2][arow] = av.z;
        As[acol + 3][arow] = av.w;

        if (TRANSB) {
            const int bn = tid >> 1;
            const int bk = (tid & 1) * 4;
            float4 bv = *reinterpret_cast<const float4*>(
                &Bp[(long long)(n0 + bn) * ldb + k0 + bk]);
            Bs[bk + 0][bn] = bv.x;
            Bs[bk + 1][bn] = bv.y;
            Bs[bk + 2][bn] = bv.z;
            Bs[bk + 3][bn] = bv.w;
        } else {
            const int bk = tid >> 5;
            const int bn = (tid & 31) * 4;
            float4 bv = *reinterpret_cast<const float4*>(
                &Bp[(long long)(k0 + bk) * ldb + n0 + bn]);
            *reinterpret_cast<float4*>(&Bs[bk][bn]) = bv;
        }
        __syncthreads();

        #pragma unroll
        for (int kk = 0; kk < BK; kk++) {
            float a[8], b[8];
            #pragma unroll
            for (int i = 0; i < 4; i++) {
                a[i]     = As[kk][ty * 4 + i];
                a[i + 4] = As[kk][64 + ty * 4 + i];
            }
            #pragma unroll
            for (int j = 0; j < 4; j++) {
                b[j]     = Bs[kk][tx * 4 + j];
                b[j + 4] = Bs[kk][64 + tx * 4 + j];
            }
            #pragma unroll
            for (int i = 0; i < 8; i++)
                #pragma unroll
                for (int j = 0; j < 8; j++)
                    acc[i][j] += a[i] * b[j];
        }
        __syncthreads();
    }

    // write back (two float4 per row)
    #pragma unroll
    for (int i = 0; i < 8; i++) {
        const int m = m0 + ((i < 4) ? (ty * 4 + i) : (64 + ty * 4 + (i - 4)));
        #pragma unroll
        for (int half = 0; half < 2; half++) {
            const int n = n0 + tx * 4 + half * 64;
            long long idx = (long long)m * ldc + n;
            float4 v;
            v.x = alpha * acc[i][half * 4 + 0];
            v.y = alpha * acc[i][half * 4 + 1];
            v.z = alpha * acc[i][half * 4 + 2];
            v.w = alpha * acc[i][half * 4 + 3];
            if (ACC) {
                float4 c = *reinterpret_cast<const float4*>(&C[idx]);
                v.x += c.x; v.y += c.y; v.z += c.z; v.w += c.w;
            }
            *reinterpret_cast<float4*>(&C[idx]) = v;
        }
    }
}

// ---------------------------------------------------------------------------
// Causal softmax in place over rows of S (B,T,T). Writes zeros for s>t up to
// the next 128 boundary (the only region the capped P@V GEMM can read).
// ---------------------------------------------------------------------------
__global__ void __launch_bounds__(256)
softmax_causal_kernel(float* __restrict__ S)
{
    __shared__ float red[256];
    const int r = blockIdx.x;          // 0..BT-1
    const int b = r / TT, t = r % TT;
    float* row = S + (long long)b * TT * TT + (long long)t * TT;
    const int valid = t + 1;
    const int tid = threadIdx.x;

    float mx = -1e30f;
    for (int s = tid; s < valid; s += 256) mx = fmaxf(mx, row[s]);
    red[tid] = mx; __syncthreads();
    for (int o = 128; o > 0; o >>= 1) {
        if (tid < o) red[tid] = fmaxf(red[tid], red[tid + o]);
        __syncthreads();
    }
    mx = red[0]; __syncthreads();

    float sum = 0.f;
    for (int s = tid; s < valid; s += 256) {
        float e = expf(row[s] - mx);
        row[s] = e;
        sum += e;
    }
    red[tid] = sum; __syncthreads();
    for (int o = 128; o > 0; o >>= 1) {
        if (tid < o) red[tid] += red[tid + o];
        __syncthreads();
    }
    const float inv = 1.f / red[0];

    for (int s = tid; s < valid; s += 256) row[s] *= inv;
    const int zend = ((valid + 127) / 128) * 128;     // tile boundary; rest never read
    for (int s = valid + tid; s < zend; s += 256) row[s] = 0.f;
}

// ---------------------------------------------------------------------------
// Combine: gate = sigmoid(In . gw + gb); v = softplus(sp)*mask*gate*(O - In)
// seq mode: seq += v (or seq = v if seq_init); delta mode: delta = v
// ---------------------------------------------------------------------------
__global__ void __launch_bounds__(256)
combine_kernel(const float* __restrict__ In, const float* __restrict__ O,
               const float* __restrict__ gw, const float* __restrict__ gb,
               const float* __restrict__ sp, float mask,
               float* __restrict__ seq, float* __restrict__ delta, int seq_init)
{
    __shared__ float red[256];
    const int r = blockIdx.x;
    const long long base = (long long)r * DD;
    const int tid = threadIdx.x;

    float dot = 0.f;
    for (int d = tid; d < DD; d += 256) dot += In[base + d] * gw[d];
    red[tid] = dot; __syncthreads();
    for (int o = 128; o > 0; o >>= 1) {
        if (tid < o) red[tid] += red[tid + o];
        __syncthreads();
    }
    const float zv = red[0] + gb[0];
    const float gate = 1.f / (1.f + expf(-zv));
    const float s = sp[0];
    float coef = (s > 20.f) ? s : log1pf(expf(s));   // softplus
    coef *= mask * gate;

    for (int d = tid; d < DD; d += 256) {
        const float v = coef * (O[base + d] - In[base + d]);
        if (delta) delta[base + d] = v;
        if (seq)   seq[base + d] = seq_init ? v : (seq[base + d] + v);
    }
}

// ---------------------------------------------------------------------------
// Elementwise add: c = a + b
// ---------------------------------------------------------------------------
__global__ void add_kernel(const float* __restrict__ a, const float* __restrict__ b,
                           float* __restrict__ c, int n)
{
    int i = blockIdx.x * 256 + threadIdx.x;
    if (i < n) c[i] = a[i] + b[i];
}

// ---------------------------------------------------------------------------
// LayerNorm (per row of D=768)
// ---------------------------------------------------------------------------
__global__ void __launch_bounds__(256)
ln_kernel(const float* __restrict__ x, const float* __restrict__ g,
          const float* __restrict__ b, float* __restrict__ out)
{
    __shared__ float r1[256], r2[256];
    const int r = blockIdx.x;
    const long long base = (long long)r * DD;
    const int tid = threadIdx.x;

    float s = 0.f, s2 = 0.f;
    for (int d = tid; d < DD; d += 256) {
        float v = x[base + d];
        s += v; s2 += v * v;
    }
    r1[tid] = s; r2[tid] = s2; __syncthreads();
    for (int o = 128; o > 0; o >>= 1) {
        if (tid < o) { r1[tid] += r1[tid + o]; r2[tid] += r2[tid + o]; }
        __syncthreads();
    }
    const float m   = r1[0] / DD;
    const float var = r2[0] / DD - m * m;
    const float inv = rsqrtf(var + 1e-5f);
    for (int d = tid; d < DD; d += 256)
        out[base + d] = (x[base + d] - m) * inv * g[d] + b[d];
}

// ---------------------------------------------------------------------------
// Finalize: e = (1-mg)*seq + mg*par; LN(e); out = x + rg*LN(e)
// ---------------------------------------------------------------------------
__global__ void __launch_bounds__(256)
final_kernel(const float* __restrict__ x, const float* __restrict__ seq,
             const float* __restrict__ par, const float* __restrict__ g,
             const float* __restrict__ b, const float* __restrict__ mode_logit,
             const float* __restrict__ res_gate, float* __restrict__ out)
{
    __shared__ float r1[256], r2[256];
    const int r = blockIdx.x;
    const long long base = (long long)r * DD;
    const int tid = threadIdx.x;

    const float mg = 1.f / (1.f + expf(-mode_logit[0]));
    const float rg = res_gate[0];

    float s = 0.f, s2 = 0.f;
    for (int d = tid; d < DD; d += 256) {
        float e = (1.f - mg) * seq[base + d] + mg * par[base + d];
        s += e; s2 += e * e;
    }
    r1[tid] = s; r2[tid] = s2; __syncthreads();
    for (int o = 128; o > 0; o >>= 1) {
        if (tid < o) { r1[tid] += r1[tid + o]; r2[tid] += r2[tid + o]; }
        __syncthreads();
    }
    const float m   = r1[0] / DD;
    const float var = r2[0] / DD - m * m;
    const float inv = rsqrtf(var + 1e-5f);
    for (int d = tid; d < DD; d += 256) {
        float e  = (1.f - mg) * seq[base + d] + mg * par[base + d];
        float ln = (e - m) * inv * g[d] + b[d];
        out[base + d] = x[base + d] + rg * ln;
    }
}

// ---------------------------------------------------------------------------
// Host-side chamber driver
// ---------------------------------------------------------------------------
static void run_chamber(const float* In, const float* Wq, const float* Wk,
                        const float* gw, const float* gb, const float* sp,
                        float mask, float* q, float* k, float* S, float* o,
                        float* seq, float* delta, int seq_init)
{
    const float inv_sqrt_d = 1.f / sqrtf((float)DD);

    // Q = In @ Wq, K = In @ Wk   (4096 x 768 x 768, NN)
    sgemm_kernel<false, false, false, false>
        <<<dim3(DD / 128, BT / 128, 1), 256>>>(
            In, DD, 0, Wq, DD, 0, q, DD, 0, BT, DD, DD, 1.f);
    sgemm_kernel<false, false, false, false>
        <<<dim3(DD / 128, BT / 128, 1), 256>>>(
            In, DD, 0, Wk, DD, 0, k, DD, 0, BT, DD, DD, 1.f);

    // S = Q @ K^T / sqrt(D)  per batch (1024x1024x768, NT, skip upper tiles)
    sgemm_kernel<true, false, true, false>
        <<<dim3(TT / 128, TT / 128, BB), 256>>>(
            q, DD, (long long)TT * DD, k, DD, (long long)TT * DD,
            S, TT, (long long)TT * TT, TT, TT, DD, inv_sqrt_d);

    // causal softmax in place
    softmax_causal_kernel<<<BT, 256>>>(S);

    // O = P @ In  per batch (1024x768x1024, NN, K loop capped at diagonal)
    sgemm_kernel<false, false, false, true>
        <<<dim3(DD / 128, TT / 128, BB), 256>>>(
            S, TT, (long long)TT * TT, In, DD, (long long)TT * DD,
            o, DD, (long long)TT * DD, TT, DD, TT, 1.f);

    // gated combine
    combine_kernel<<<BT, 256>>>(In, o, gw, gb, sp, mask, seq, delta, seq_init);
}

extern "C" void kernel_launch(void* const* d_in, const int* in_sizes, int n_in,
                              void* d_out, int out_size)
{
    const float* x             = (const float*)d_in[0];
    const float* Wq            = (const float*)d_in[1];
    const float* Wk            = (const float*)d_in[2];
    const float* gate_w        = (const float*)d_in[3];
    const float* gate_b        = (const float*)d_in[4];
    const float* scale_p       = (const float*)d_in[5];
    const float* merge_W       = (const float*)d_in[6];
    const float* mode_logit    = (const float*)d_in[7];
    const float* residual_gate = (const float*)d_in[8];
    const float* ln_pre_g      = (const float*)d_in[9];
    const float* ln_pre_b      = (const float*)d_in[10];
    const float* ln_post_g     = (const float*)d_in[11];
    const float* ln_post_b     = (const float*)d_in[12];
    float* out = (float*)d_out;

    float *h, *inb, *q, *k, *o, *seq, *delta, *par, *S;
    cudaGetSymbolAddress((void**)&h,     g_h);
    cudaGetSymbolAddress((void**)&inb,   g_in);
    cudaGetSymbolAddress((void**)&q,     g_q);
    cudaGetSymbolAddress((void**)&k,     g_k);
    cudaGetSymbolAddress((void**)&o,     g_o);
    cudaGetSymbolAddress((void**)&seq,   g_seq);
    cudaGetSymbolAddress((void**)&delta, g_delta);
    cudaGetSymbolAddress((void**)&par,   g_par);
    cudaGetSymbolAddress((void**)&S,     g_S);

    // Curriculum masks (static host constants): sigmoid(slope*(STEP - WARMUP*(i+0.5)/N))
    float maskv[NCH];
    {
        const double slope = 8.0 * NCH / 2000.0;
        for (int i = 0; i < NCH; i++) {
            double a = slope * (4000.0 - 2000.0 * (i + 0.5) / NCH);
            maskv[i] = (float)(1.0 / (1.0 + exp(-a)));
        }
    }

    // h = LN_pre(x)
    ln_kernel<<<BT, 256>>>(x, ln_pre_g, ln_pre_b, h);

    // ---- parallel chamber 0: delta_0, which also equals seq after i=0 ----
    run_chamber(h, Wq, Wk, gate_w, gate_b, scale_p, maskv[0],
                q, k, S, o, seq, delta, /*seq_init=*/1);
    // par = delta_0 @ M_0  (TRANSB against merge_W slice, ldb = N*D)
    sgemm_kernel<true, false, false, false>
        <<<dim3(DD / 128, BT / 128, 1), 256>>>(
            delta, DD, 0, merge_W, NCH * DD, 0, par, DD, 0, BT, DD, DD, 1.f);

    // ---- parallel chambers 1..6 (input h), accumulate merge into par ----
    for (int i = 1; i < NCH; i++) {
        run_chamber(h, Wq + (size_t)i * DD * DD, Wk + (size_t)i * DD * DD,
                    gate_w + (size_t)i * DD, gate_b + i, scale_p + i, maskv[i],
                    q, k, S, o, /*seq=*/nullptr, delta, 0);
        sgemm_kernel<true, true, false, false>
            <<<dim3(DD / 128, BT / 128, 1), 256>>>(
                delta, DD, 0, merge_W + (size_t)i * DD, NCH * DD, 0,
                par, DD, 0, BT, DD, DD, 1.f);
    }

    // ---- sequential chambers 1..6 (input h + seq) ----
    const int nelem = BT * DD;
    for (int i = 1; i < NCH; i++) {
        add_kernel<<<(nelem + 255) / 256, 256>>>(h, seq, inb, nelem);
        run_chamber(inb, Wq + (size_t)i * DD * DD, Wk + (size_t)i * DD * DD,
                    gate_w + (size_t)i * DD, gate_b + i, scale_p + i, maskv[i],
                    q, k, S, o, seq, /*delta=*/nullptr, 0);
    }

    // ---- finalize: mix, LN_post, residual ----
    final_kernel<<<BT, 256>>>(x, seq, par, ln_post_g, ln_post_b,
                              mode_logit, residual_gate, out);
}

// round 7
// speedup vs baseline: 3.5289x; 3.5289x over previous
#include <cuda_runtime.h>
#include <stdint.h>
#include <math.h>

// Problem constants
#define BB  4
#define TT  1024
#define DD  768
#define NCH 7
#define BT  (BB*TT)   // 4096 rows

// ---------------------------------------------------------------------------
// Scratch (device globals; no allocation allowed in kernel_launch)
// ---------------------------------------------------------------------------
__device__ float g_h   [(size_t)BT*DD];
__device__ float g_in  [(size_t)BT*DD];
__device__ float g_seq [(size_t)BT*DD];
__device__ float g_par [(size_t)BT*DD];
__device__ float g_q   [(size_t)NCH*BT*DD];   // 88 MB
__device__ float g_k   [(size_t)NCH*BT*DD];
__device__ float g_o   [(size_t)NCH*BT*DD];
__device__ float g_d   [(size_t)NCH*BT*DD];
__device__ float g_S   [(size_t)NCH*BB*TT*TT]; // 117 MB

// ---------------------------------------------------------------------------
// TF32 helpers
// ---------------------------------------------------------------------------
__device__ __forceinline__ uint32_t f2tf(float f) {
    uint32_t r;
    asm("cvt.rna.tf32.f32 %0, %1;" : "=r"(r) : "f"(f));
    return r;
}
__device__ __forceinline__ void mma_tf32(float c[4],
    uint32_t a0, uint32_t a1, uint32_t a2, uint32_t a3,
    uint32_t b0, uint32_t b1)
{
    asm volatile(
        "mma.sync.aligned.m16n8k8.row.col.f32.tf32.tf32.f32 "
        "{%0,%1,%2,%3}, {%4,%5,%6,%7}, {%8,%9}, {%0,%1,%2,%3};"
        : "+f"(c[0]), "+f"(c[1]), "+f"(c[2]), "+f"(c[3])
        : "r"(a0), "r"(a1), "r"(a2), "r"(a3), "r"(b0), "r"(b1));
}
#define CPA16(saddr, gptr) \
    asm volatile("cp.async.cg.shared.global [%0], [%1], 16;" :: "r"(saddr), "l"(gptr))
#define CPA_COMMIT() asm volatile("cp.async.commit_group;")
#define CPA_WAIT0()  asm volatile("cp.async.wait_group 0;")

// ---------------------------------------------------------------------------
// TF32 MMA GEMM: C = alpha * A @ op(B) (+ C if ACC)
//   A: M x K row-major (lda). If kchunk>0: A[m, k] := Abase[(k/kchunk)*schunk
//      + m*lda + k%kchunk]  (K-concat of chunked tensors, for the merge GEMM)
//   B: TRANSB ? (N x K row-major, ldb) : (K x N row-major, ldb)
//   batched over blockIdx.z with strides sA/sB/sC; bmod>0 -> B uses z%bmod
//   CSKIP: skip C tiles fully above the diagonal (causal QK^T)
//   CKLIM: A[m,k]==0 for k>=ceil128(m) -> cap K loop at tile diagonal (P@V)
// Tiles: BM=BN=128, BK=16. 256 threads = 8 warps (2x4), warp tile 64x32,
// 4x4 m16n8k8 fragments per warp. cp.async double buffer.
// All M,N %128==0 and K %16==0 (true for every launch here).
// ---------------------------------------------------------------------------
#define ASTRIDE 20    // [128][20] m-major, conflict-free fragment reads
#define BSTRIDE 136   // [16][136] k-major (non-trans B)
#define AS_SZ  (128*ASTRIDE)   // 2560 floats
#define STG_SZ (2*AS_SZ)       // A region + B region (B needs max 2560)

template<bool TRANSB, bool ACC, bool CSKIP, bool CKLIM>
__global__ void __launch_bounds__(256)
mma_gemm(const float* __restrict__ A, int lda, long long sA,
         const float* __restrict__ Bp, int ldb, long long sB, int bmod,
         float* __restrict__ C, int ldc, long long sC,
         int M, int N, int K, float alpha,
         int kchunk, long long schunk)
{
    const int m0 = blockIdx.y * 128;
    const int n0 = blockIdx.x * 128;
    if (CSKIP && n0 > m0 + 127) return;

    const int z = blockIdx.z;
    A  += (long long)z * sA;
    Bp += (long long)(bmod ? (z % bmod) : z) * sB;
    C  += (long long)z * sC;

    int kend = K;
    if (CKLIM) { int ke = m0 + 128; kend = (ke < K) ? ke : K; }
    const int niter = kend >> 4;

    __shared__ float sm[2][STG_SZ];

    const int tid  = threadIdx.x;
    const int wid  = tid >> 5;
    const int lane = tid & 31;
    const int gid  = lane >> 2;
    const int tig  = lane & 3;
    const int wm   = (wid & 1) * 64;
    const int wn   = (wid >> 1) * 32;

    float acc[4][4][4];
    #pragma unroll
    for (int i = 0; i < 4; i++)
        #pragma unroll
        for (int j = 0; j < 4; j++)
            #pragma unroll
            for (int r = 0; r < 4; r++) acc[i][j][r] = 0.f;

    auto loadA = [&](int stg, int k0) {
        const float* Ab;
        if (kchunk) { int c = k0 / kchunk; Ab = A + (long long)c * schunk + (k0 - c * kchunk); }
        else        Ab = A + k0;
        float* as = sm[stg];
        #pragma unroll
        for (int i = 0; i < 2; i++) {
            int idx = tid + i * 256;
            int r = idx >> 2, c4 = (idx & 3) << 2;
            uint32_t sa = (uint32_t)__cvta_generic_to_shared(&as[r * ASTRIDE + c4]);
            CPA16(sa, Ab + (long long)(m0 + r) * lda + c4);
        }
    };
    auto loadB = [&](int stg, int k0) {
        float* bs = sm[stg] + AS_SZ;
        if (TRANSB) {
            #pragma unroll
            for (int i = 0; i < 2; i++) {
                int idx = tid + i * 256;
                int r = idx >> 2, c4 = (idx & 3) << 2;
                uint32_t sa = (uint32_t)__cvta_generic_to_shared(&bs[r * ASTRIDE + c4]);
                CPA16(sa, Bp + (long long)(n0 + r) * ldb + k0 + c4);
            }
        } else {
            #pragma unroll
            for (int i = 0; i < 2; i++) {
                int idx = tid + i * 256;
                int r = idx >> 5, c4 = (idx & 31) << 2;
                uint32_t sa = (uint32_t)__cvta_generic_to_shared(&bs[r * BSTRIDE + c4]);
                CPA16(sa, Bp + (long long)(k0 + r) * ldb + n0 + c4);
            }
        }
    };

    loadA(0, 0); loadB(0, 0);
    CPA_COMMIT();

    for (int it = 0; it < niter; ++it) {
        CPA_WAIT0();
        __syncthreads();
        if (it + 1 < niter) {
            loadA((it + 1) & 1, (it + 1) << 4);
            loadB((it + 1) & 1, (it + 1) << 4);
            CPA_COMMIT();
        }
        const float* as = sm[it & 1];
        const float* bs = as + AS_SZ;

        #pragma unroll
        for (int kk = 0; kk < 16; kk += 8) {
            uint32_t a[4][4];
            #pragma unroll
            for (int mi = 0; mi < 4; mi++) {
                int mb = wm + mi * 16 + gid;
                a[mi][0] = f2tf(as[ mb      * ASTRIDE + kk + tig    ]);
                a[mi][1] = f2tf(as[(mb + 8) * ASTRIDE + kk + tig    ]);
                a[mi][2] = f2tf(as[ mb      * ASTRIDE + kk + tig + 4]);
                a[mi][3] = f2tf(as[(mb + 8) * ASTRIDE + kk + tig + 4]);
            }
            uint32_t b[4][2];
            #pragma unroll
            for (int ni = 0; ni < 4; ni++) {
                int nb = wn + ni * 8 + gid;
                if (TRANSB) {
                    b[ni][0] = f2tf(bs[nb * ASTRIDE + kk + tig    ]);
                    b[ni][1] = f2tf(bs[nb * ASTRIDE + kk + tig + 4]);
                } else {
                    b[ni][0] = f2tf(bs[(kk + tig    ) * BSTRIDE + nb]);
                    b[ni][1] = f2tf(bs[(kk + tig + 4) * BSTRIDE + nb]);
                }
            }
            #pragma unroll
            for (int mi = 0; mi < 4; mi++)
                #pragma unroll
                for (int ni = 0; ni < 4; ni++)
                    mma_tf32(acc[mi][ni], a[mi][0], a[mi][1], a[mi][2], a[mi][3],
                             b[ni][0], b[ni][1]);
        }
    }

    // epilogue: c0 (g, 2t), c1 (g, 2t+1), c2 (g+8, 2t), c3 (g+8, 2t+1)
    #pragma unroll
    for (int mi = 0; mi < 4; mi++) {
        #pragma unroll
        for (int ni = 0; ni < 4; ni++) {
            const int rr = m0 + wm + mi * 16 + gid;
            const int cc = n0 + wn + ni * 8 + tig * 2;
            #pragma unroll
            for (int hh = 0; hh < 2; hh++) {
                long long idx = (long long)(rr + hh * 8) * ldc + cc;
                float2 v;
                v.x = alpha * acc[mi][ni][hh * 2 + 0];
                v.y = alpha * acc[mi][ni][hh * 2 + 1];
                if (ACC) {
                    float2 c = *reinterpret_cast<const float2*>(&C[idx]);
                    v.x += c.x; v.y += c.y;
                }
                *reinterpret_cast<float2*>(&C[idx]) = v;
            }
        }
    }
}

// ---------------------------------------------------------------------------
// Causal softmax in place over rows of S ([nz][T][T]). Zeroes (t, tileEnd).
// ---------------------------------------------------------------------------
__global__ void __launch_bounds__(256)
softmax_causal_kernel(float* __restrict__ S)
{
    __shared__ float red[256];
    const int r = blockIdx.x;
    const int zb = r / TT, t = r % TT;
    float* row = S + (long long)zb * TT * TT + (long long)t * TT;
    const int valid = t + 1;
    const int tid = threadIdx.x;

    float mx = -1e30f;
    for (int s = tid; s < valid; s += 256) mx = fmaxf(mx, row[s]);
    red[tid] = mx; __syncthreads();
    for (int o = 128; o > 0; o >>= 1) {
        if (tid < o) red[tid] = fmaxf(red[tid], red[tid + o]);
        __syncthreads();
    }
    mx = red[0]; __syncthreads();

    float sum = 0.f;
    for (int s = tid; s < valid; s += 256) {
        float e = expf(row[s] - mx);
        row[s] = e;
        sum += e;
    }
    red[tid] = sum; __syncthreads();
    for (int o = 128; o > 0; o >>= 1) {
        if (tid < o) red[tid] += red[tid + o];
        __syncthreads();
    }
    const float inv = 1.f / red[0];

    for (int s = tid; s < valid; s += 256) row[s] *= inv;
    const int zend = ((valid + 127) / 128) * 128;
    for (int s = valid + tid; s < zend; s += 256) row[s] = 0.f;
}

// ---------------------------------------------------------------------------
// Batched parallel combine: chamber i = blockIdx.y.
// v = softplus(sp[i]) * sigmoid(h.gw_i + gb_i) * (O_i - h); delta_i = v;
// chamber 0 also initializes seq = v.  (curriculum masks are exactly 1.0f)
// ---------------------------------------------------------------------------
__global__ void __launch_bounds__(256)
combine_par_kernel(const float* __restrict__ hIn, const float* __restrict__ o7,
                   const float* __restrict__ gw, const float* __restrict__ gb,
                   const float* __restrict__ sp,
                   float* __restrict__ delta7, float* __restrict__ seq)
{
    __shared__ float red[256];
    const int i = blockIdx.y;
    const int r = blockIdx.x;
    const long long base = (long long)r * DD;
    const long long cbase = (long long)i * BT * DD + base;
    const int tid = threadIdx.x;
    const float* gwi = gw + (size_t)i * DD;

    float dot = 0.f;
    for (int d = tid; d < DD; d += 256) dot += hIn[base + d] * gwi[d];
    red[tid] = dot; __syncthreads();
    for (int o = 128; o > 0; o >>= 1) {
        if (tid < o) red[tid] += red[tid + o];
        __syncthreads();
    }
    const float gate = 1.f / (1.f + expf(-(red[0] + gb[i])));
    const float s = sp[i];
    float coef = (s > 20.f) ? s : log1pf(expf(s));
    coef *= gate;

    for (int d = tid; d < DD; d += 256) {
        const float v = coef * (o7[cbase + d] - hIn[base + d]);
        delta7[cbase + d] = v;
        if (i == 0) seq[base + d] = v;
    }
}

// ---------------------------------------------------------------------------
// Sequential combine: seq += softplus(sp)*sigmoid(In.gw+gb)*(O-In)
// ---------------------------------------------------------------------------
__global__ void __launch_bounds__(256)
combine_seq_kernel(const float* __restrict__ In, const float* __restrict__ O,
                   const float* __restrict__ gw, const float* __restrict__ gb,
                   const float* __restrict__ sp, float* __restrict__ seq)
{
    __shared__ float red[256];
    const int r = blockIdx.x;
    const long long base = (long long)r * DD;
    const int tid = threadIdx.x;

    float dot = 0.f;
    for (int d = tid; d < DD; d += 256) dot += In[base + d] * gw[d];
    red[tid] = dot; __syncthreads();
    for (int o = 128; o > 0; o >>= 1) {
        if (tid < o) red[tid] += red[tid + o];
        __syncthreads();
    }
    const float gate = 1.f / (1.f + expf(-(red[0] + gb[0])));
    const float s = sp[0];
    float coef = (s > 20.f) ? s : log1pf(expf(s));
    coef *= gate;

    for (int d = tid; d < DD; d += 256)
        seq[base + d] += coef * (O[base + d] - In[base + d]);
}

// ---------------------------------------------------------------------------
__global__ void add_kernel(const float* __restrict__ a, const float* __restrict__ b,
                           float* __restrict__ c, int n)
{
    int i = blockIdx.x * 256 + threadIdx.x;
    if (i < n) c[i] = a[i] + b[i];
}

// ---------------------------------------------------------------------------
__global__ void __launch_bounds__(256)
ln_kernel(const float* __restrict__ x, const float* __restrict__ g,
          const float* __restrict__ b, float* __restrict__ out)
{
    __shared__ float r1[256], r2[256];
    const int r = blockIdx.x;
    const long long base = (long long)r * DD;
    const int tid = threadIdx.x;

    float s = 0.f, s2 = 0.f;
    for (int d = tid; d < DD; d += 256) {
        float v = x[base + d];
        s += v; s2 += v * v;
    }
    r1[tid] = s; r2[tid] = s2; __syncthreads();
    for (int o = 128; o > 0; o >>= 1) {
        if (tid < o) { r1[tid] += r1[tid + o]; r2[tid] += r2[tid + o]; }
        __syncthreads();
    }
    const float m   = r1[0] / DD;
    const float var = r2[0] / DD - m * m;
    const float inv = rsqrtf(var + 1e-5f);
    for (int d = tid; d < DD; d += 256)
        out[base + d] = (x[base + d] - m) * inv * g[d] + b[d];
}

// ---------------------------------------------------------------------------
__global__ void __launch_bounds__(256)
final_kernel(const float* __restrict__ x, const float* __restrict__ seq,
             const float* __restrict__ par, const float* __restrict__ g,
             const float* __restrict__ b, const float* __restrict__ mode_logit,
             const float* __restrict__ res_gate, float* __restrict__ out)
{
    __shared__ float r1[256], r2[256];
    const int r = blockIdx.x;
    const long long base = (long long)r * DD;
    const int tid = threadIdx.x;

    const float mg = 1.f / (1.f + expf(-mode_logit[0]));
    const float rg = res_gate[0];

    float s = 0.f, s2 = 0.f;
    for (int d = tid; d < DD; d += 256) {
        float e = (1.f - mg) * seq[base + d] + mg * par[base + d];
        s += e; s2 += e * e;
    }
    r1[tid] = s; r2[tid] = s2; __syncthreads();
    for (int o = 128; o > 0; o >>= 1) {
        if (tid < o) { r1[tid] += r1[tid + o]; r2[tid] += r2[tid + o]; }
        __syncthreads();
    }
    const float m   = r1[0] / DD;
    const float var = r2[0] / DD - m * m;
    const float inv = rsqrtf(var + 1e-5f);
    for (int d = tid; d < DD; d += 256) {
        float e  = (1.f - mg) * seq[base + d] + mg * par[base + d];
        float ln = (e - m) * inv * g[d] + b[d];
        out[base + d] = x[base + d] + rg * ln;
    }
}

// ---------------------------------------------------------------------------
extern "C" void kernel_launch(void* const* d_in, const int* in_sizes, int n_in,
                              void* d_out, int out_size)
{
    const float* x             = (const float*)d_in[0];
    const float* Wq            = (const float*)d_in[1];
    const float* Wk            = (const float*)d_in[2];
    const float* gate_w        = (const float*)d_in[3];
    const float* gate_b        = (const float*)d_in[4];
    const float* scale_p       = (const float*)d_in[5];
    const float* merge_W       = (const float*)d_in[6];
    const float* mode_logit    = (const float*)d_in[7];
    const float* residual_gate = (const float*)d_in[8];
    const float* ln_pre_g      = (const float*)d_in[9];
    const float* ln_pre_b      = (const float*)d_in[10];
    const float* ln_post_g     = (const float*)d_in[11];
    const float* ln_post_b     = (const float*)d_in[12];
    float* out = (float*)d_out;

    float *h, *inb, *seq, *par, *q, *k, *o, *dl, *S;
    cudaGetSymbolAddress((void**)&h,   g_h);
    cudaGetSymbolAddress((void**)&inb, g_in);
    cudaGetSymbolAddress((void**)&seq, g_seq);
    cudaGetSymbolAddress((void**)&par, g_par);
    cudaGetSymbolAddress((void**)&q,   g_q);
    cudaGetSymbolAddress((void**)&k,   g_k);
    cudaGetSymbolAddress((void**)&o,   g_o);
    cudaGetSymbolAddress((void**)&dl,  g_d);
    cudaGetSymbolAddress((void**)&S,   g_S);

    const float isd = 1.f / sqrtf((float)DD);
    const long long sQK  = (long long)DD * DD;   // Wq/Wk chamber stride
    const long long sRow = (long long)BT * DD;   // per-chamber activation stride
    const long long sBT  = (long long)TT * DD;   // per-(chamber,batch) activation stride
    const long long sS   = (long long)TT * TT;

    // h = LN_pre(x)
    ln_kernel<<<BT, 256>>>(x, ln_pre_g, ln_pre_b, h);

    // ================= parallel branch: all 7 chambers batched =============
    // Q_i = h @ Wq_i, K_i = h @ Wk_i   (z = 7)
    mma_gemm<false, false, false, false><<<dim3(6, 32, NCH), 256>>>(
        h, DD, 0, Wq, DD, sQK, 0, q, DD, sRow, BT, DD, DD, 1.f, 0, 0);
    mma_gemm<false, false, false, false><<<dim3(6, 32, NCH), 256>>>(
        h, DD, 0, Wk, DD, sQK, 0, k, DD, sRow, BT, DD, DD, 1.f, 0, 0);
    // S = Q K^T / sqrt(D)  (z = 28 = chamber*4 + batch, causal tile skip)
    mma_gemm<true, false, true, false><<<dim3(8, 8, NCH * BB), 256>>>(
        q, DD, sBT, k, DD, sBT, 0, S, TT, sS, TT, TT, DD, isd, 0, 0);
    softmax_causal_kernel<<<NCH * BB * TT, 256>>>(S);
    // O = P @ h  (z = 28; B = h repeats every 4 via bmod)
    mma_gemm<false, false, false, true><<<dim3(6, 8, NCH * BB), 256>>>(
        S, TT, sS, h, DD, sBT, BB, o, DD, sBT, TT, DD, TT, 1.f, 0, 0);
    // deltas + seq init (chamber 0)
    combine_par_kernel<<<dim3(BT, NCH), 256>>>(h, o, gate_w, gate_b, scale_p, dl, seq);
    // par = concat(deltas) @ merge_W^T — single GEMM, K = 7*768, A chunked
    mma_gemm<true, false, false, false><<<dim3(6, 32, 1), 256>>>(
        dl, DD, 0, merge_W, NCH * DD, 0, 0, par, DD, 0,
        BT, DD, NCH * DD, 1.f, DD, sRow);

    // ================= sequential branch: chambers 1..6 ====================
    const int nelem = BT * DD;
    for (int i = 1; i < NCH; i++) {
        add_kernel<<<(nelem + 255) / 256, 256>>>(h, seq, inb, nelem);
        mma_gemm<false, false, false, false><<<dim3(6, 32, 1), 256>>>(
            inb, DD, 0, Wq + (size_t)i * DD * DD, DD, 0, 0,
            q, DD, 0, BT, DD, DD, 1.f, 0, 0);
        mma_gemm<false, false, false, false><<<dim3(6, 32, 1), 256>>>(
            inb, DD, 0, Wk + (size_t)i * DD * DD, DD, 0, 0,
            k, DD, 0, BT, DD, DD, 1.f, 0, 0);
        mma_gemm<true, false, true, false><<<dim3(8, 8, BB), 256>>>(
            q, DD, sBT, k, DD, sBT, 0, S, TT, sS, TT, TT, DD, isd, 0, 0);
        softmax_causal_kernel<<<BB * TT, 256>>>(S);
        mma_gemm<false, false, false, true><<<dim3(6, 8, BB), 256>>>(
            S, TT, sS, inb, DD, sBT, 0, o, DD, sBT, TT, DD, TT, 1.f, 0, 0);
        combine_seq_kernel<<<BT, 256>>>(inb, o, gate_w + (size_t)i * DD,
                                        gate_b + i, scale_p + i, seq);
    }

    // ================= finalize ============================================
    final_kernel<<<BT, 256>>>(x, seq, par, ln_post_g, ln_post_b,
                              mode_logit, residual_gate, out);
}

// round 8
// speedup vs baseline: 4.0488x; 1.1473x over previous
#include <cuda_runtime.h>
#include <stdint.h>
#include <math.h>

// Problem constants
#define BB  4
#define TT  1024
#define DD  768
#define NCH 7
#define BT  (BB*TT)   // 4096 rows

// ---------------------------------------------------------------------------
// Scratch (device globals; no allocation allowed in kernel_launch)
// ---------------------------------------------------------------------------
__device__ float g_h   [(size_t)BT*DD];
__device__ float g_in  [(size_t)BT*DD];
__device__ float g_seq [(size_t)BT*DD];
__device__ float g_par [(size_t)BT*DD];
// parallel branch (chambers indexed 0..6; chamber 0 slot of q/k/o unused)
__device__ float g_q   [(size_t)NCH*BT*DD];
__device__ float g_k   [(size_t)NCH*BT*DD];
__device__ float g_o   [(size_t)NCH*BT*DD];
__device__ float g_d   [(size_t)NCH*BT*DD];
__device__ float g_S   [(size_t)NCH*BB*TT*TT];
// sequential-branch private buffers (avoid races with concurrent s1 work)
__device__ float g_q2  [(size_t)BT*DD];
__device__ float g_k2  [(size_t)BT*DD];
__device__ float g_o2  [(size_t)BT*DD];
__device__ float g_S2  [(size_t)BB*TT*TT];
// TF32-rounded weight copies
__device__ float g_wq  [(size_t)NCH*DD*DD];
__device__ float g_wk  [(size_t)NCH*DD*DD];
__device__ float g_mw  [(size_t)DD*NCH*DD];

// ---------------------------------------------------------------------------
// TF32 helpers
// ---------------------------------------------------------------------------
__device__ __forceinline__ uint32_t f2tf(float f) {
    uint32_t r;
    asm("cvt.rna.tf32.f32 %0, %1;" : "=r"(r) : "f"(f));
    return r;
}
__device__ __forceinline__ float tf32r(float f) { return __uint_as_float(f2tf(f)); }

__device__ __forceinline__ void mma_tf32(float c[4],
    uint32_t a0, uint32_t a1, uint32_t a2, uint32_t a3,
    uint32_t b0, uint32_t b1)
{
    asm volatile(
        "mma.sync.aligned.m16n8k8.row.col.f32.tf32.tf32.f32 "
        "{%0,%1,%2,%3}, {%4,%5,%6,%7}, {%8,%9}, {%0,%1,%2,%3};"
        : "+f"(c[0]), "+f"(c[1]), "+f"(c[2]), "+f"(c[3])
        : "r"(a0), "r"(a1), "r"(a2), "r"(a3), "r"(b0), "r"(b1));
}
#define CPA16(saddr, gptr) \
    asm volatile("cp.async.cg.shared.global [%0], [%1], 16;" :: "r"(saddr), "l"(gptr))
#define CPA_COMMIT() asm volatile("cp.async.commit_group;")
#define CPA_WAIT0()  asm volatile("cp.async.wait_group 0;")

// ---------------------------------------------------------------------------
// TF32 MMA GEMM: C = round_tf32( alpha * A @ op(B) (+ C if ACC) )
// ALL operands must already be TF32-rounded fp32 (producers round at write).
// No cvt in the inner loop — raw bit reinterpretation.
//   A: M x K row-major (lda). kchunk>0: K-concat of chunks (merge GEMM).
//   B: TRANSB ? N x K row-major : K x N row-major. bmod>0 -> B uses z%bmod.
//   CSKIP: skip C tiles fully above diagonal. CKLIM: cap K at tile diagonal.
// Tiles 128x128x16, 8 warps, 64x32 warp tile, cp.async double buffer.
// ---------------------------------------------------------------------------
#define ASTRIDE 20
#define BSTRIDE 136
#define AS_SZ  (128*ASTRIDE)
#define STG_SZ (2*AS_SZ)

template<bool TRANSB, bool ACC, bool CSKIP, bool CKLIM>
__global__ void __launch_bounds__(256, 2)
mma_gemm(const float* __restrict__ A, int lda, long long sA,
         const float* __restrict__ Bp, int ldb, long long sB, int bmod,
         float* __restrict__ C, int ldc, long long sC,
         int M, int N, int K, float alpha,
         int kchunk, long long schunk)
{
    const int m0 = blockIdx.y * 128;
    const int n0 = blockIdx.x * 128;
    if (CSKIP && n0 > m0 + 127) return;

    const int z = blockIdx.z;
    A  += (long long)z * sA;
    Bp += (long long)(bmod ? (z % bmod) : z) * sB;
    C  += (long long)z * sC;

    int kend = K;
    if (CKLIM) { int ke = m0 + 128; kend = (ke < K) ? ke : K; }
    const int niter = kend >> 4;

    __shared__ float sm[2][STG_SZ];

    const int tid  = threadIdx.x;
    const int wid  = tid >> 5;
    const int lane = tid & 31;
    const int gid  = lane >> 2;
    const int tig  = lane & 3;
    const int wm   = (wid & 1) * 64;
    const int wn   = (wid >> 1) * 32;

    float acc[4][4][4];
    #pragma unroll
    for (int i = 0; i < 4; i++)
        #pragma unroll
        for (int j = 0; j < 4; j++)
            #pragma unroll
            for (int r = 0; r < 4; r++) acc[i][j][r] = 0.f;

    auto loadA = [&](int stg, int k0) {
        const float* Ab;
        if (kchunk) { int c = k0 / kchunk; Ab = A + (long long)c * schunk + (k0 - c * kchunk); }
        else        Ab = A + k0;
        float* as = sm[stg];
        #pragma unroll
        for (int i = 0; i < 2; i++) {
            int idx = tid + i * 256;
            int r = idx >> 2, c4 = (idx & 3) << 2;
            uint32_t sa = (uint32_t)__cvta_generic_to_shared(&as[r * ASTRIDE + c4]);
            CPA16(sa, Ab + (long long)(m0 + r) * lda + c4);
        }
    };
    auto loadB = [&](int stg, int k0) {
        float* bs = sm[stg] + AS_SZ;
        if (TRANSB) {
            #pragma unroll
            for (int i = 0; i < 2; i++) {
                int idx = tid + i * 256;
                int r = idx >> 2, c4 = (idx & 3) << 2;
                uint32_t sa = (uint32_t)__cvta_generic_to_shared(&bs[r * ASTRIDE + c4]);
                CPA16(sa, Bp + (long long)(n0 + r) * ldb + k0 + c4);
            }
        } else {
            #pragma unroll
            for (int i = 0; i < 2; i++) {
                int idx = tid + i * 256;
                int r = idx >> 5, c4 = (idx & 31) << 2;
                uint32_t sa = (uint32_t)__cvta_generic_to_shared(&bs[r * BSTRIDE + c4]);
                CPA16(sa, Bp + (long long)(k0 + r) * ldb + n0 + c4);
            }
        }
    };

    loadA(0, 0); loadB(0, 0);
    CPA_COMMIT();

    for (int it = 0; it < niter; ++it) {
        CPA_WAIT0();
        __syncthreads();
        if (it + 1 < niter) {
            loadA((it + 1) & 1, (it + 1) << 4);
            loadB((it + 1) & 1, (it + 1) << 4);
            CPA_COMMIT();
        }
        const float* as = sm[it & 1];
        const float* bs = as + AS_SZ;

        #pragma unroll
        for (int kk = 0; kk < 16; kk += 8) {
            uint32_t a[4][4];
            #pragma unroll
            for (int mi = 0; mi < 4; mi++) {
                int mb = wm + mi * 16 + gid;
                a[mi][0] = __float_as_uint(as[ mb      * ASTRIDE + kk + tig    ]);
                a[mi][1] = __float_as_uint(as[(mb + 8) * ASTRIDE + kk + tig    ]);
                a[mi][2] = __float_as_uint(as[ mb      * ASTRIDE + kk + tig + 4]);
                a[mi][3] = __float_as_uint(as[(mb + 8) * ASTRIDE + kk + tig + 4]);
            }
            uint32_t b[4][2];
            #pragma unroll
            for (int ni = 0; ni < 4; ni++) {
                int nb = wn + ni * 8 + gid;
                if (TRANSB) {
                    b[ni][0] = __float_as_uint(bs[nb * ASTRIDE + kk + tig    ]);
                    b[ni][1] = __float_as_uint(bs[nb * ASTRIDE + kk + tig + 4]);
                } else {
                    b[ni][0] = __float_as_uint(bs[(kk + tig    ) * BSTRIDE + nb]);
                    b[ni][1] = __float_as_uint(bs[(kk + tig + 4) * BSTRIDE + nb]);
                }
            }
            #pragma unroll
            for (int mi = 0; mi < 4; mi++)
                #pragma unroll
                for (int ni = 0; ni < 4; ni++)
                    mma_tf32(acc[mi][ni], a[mi][0], a[mi][1], a[mi][2], a[mi][3],
                             b[ni][0], b[ni][1]);
        }
    }

    // epilogue — output is TF32-rounded so downstream GEMMs can skip cvt
    #pragma unroll
    for (int mi = 0; mi < 4; mi++) {
        #pragma unroll
        for (int ni = 0; ni < 4; ni++) {
            const int rr = m0 + wm + mi * 16 + gid;
            const int cc = n0 + wn + ni * 8 + tig * 2;
            #pragma unroll
            for (int hh = 0; hh < 2; hh++) {
                long long idx = (long long)(rr + hh * 8) * ldc + cc;
                float2 v;
                v.x = alpha * acc[mi][ni][hh * 2 + 0];
                v.y = alpha * acc[mi][ni][hh * 2 + 1];
                if (ACC) {
                    float2 c = *reinterpret_cast<const float2*>(&C[idx]);
                    v.x += c.x; v.y += c.y;
                }
                v.x = tf32r(v.x);
                v.y = tf32r(v.y);
                *reinterpret_cast<float2*>(&C[idx]) = v;
            }
        }
    }
}

// ---------------------------------------------------------------------------
// Elementwise TF32 rounding copy (for weights), float4 vectorized
// ---------------------------------------------------------------------------
__global__ void round_tf32_kernel(const float* __restrict__ in,
                                  float* __restrict__ out, int n4)
{
    int i = blockIdx.x * 256 + threadIdx.x;
    if (i < n4) {
        float4 v = reinterpret_cast<const float4*>(in)[i];
        v.x = tf32r(v.x); v.y = tf32r(v.y); v.z = tf32r(v.z); v.w = tf32r(v.w);
        reinterpret_cast<float4*>(out)[i] = v;
    }
}

// ---------------------------------------------------------------------------
// Causal softmax in place (rows of [nz][T][T]); output TF32-rounded,
// zero-fill to 128 tile boundary.
// ---------------------------------------------------------------------------
__global__ void __launch_bounds__(256)
softmax_causal_kernel(float* __restrict__ S)
{
    __shared__ float red[256];
    const int r = blockIdx.x;
    const int zb = r / TT, t = r % TT;
    float* row = S + (long long)zb * TT * TT + (long long)t * TT;
    const int valid = t + 1;
    const int tid = threadIdx.x;

    float mx = -1e30f;
    for (int s = tid; s < valid; s += 256) mx = fmaxf(mx, row[s]);
    red[tid] = mx; __syncthreads();
    for (int o = 128; o > 0; o >>= 1) {
        if (tid < o) red[tid] = fmaxf(red[tid], red[tid + o]);
        __syncthreads();
    }
    mx = red[0]; __syncthreads();

    float sum = 0.f;
    for (int s = tid; s < valid; s += 256) {
        float e = expf(row[s] - mx);
        row[s] = e;
        sum += e;
    }
    red[tid] = sum; __syncthreads();
    for (int o = 128; o > 0; o >>= 1) {
        if (tid < o) red[tid] += red[tid + o];
        __syncthreads();
    }
    const float inv = 1.f / red[0];

    for (int s = tid; s < valid; s += 256) row[s] = tf32r(row[s] * inv);
    const int zend = ((valid + 127) / 128) * 128;
    for (int s = valid + tid; s < zend; s += 256) row[s] = 0.f;
}

// ---------------------------------------------------------------------------
// Chamber 0 combine: v = softplus(sp0)*sigmoid(h.gw0+gb0)*(O-h)
// delta0 = round(v); seq = v   (curriculum masks are exactly 1.0)
// ---------------------------------------------------------------------------
__global__ void __launch_bounds__(256)
combine_c0_kernel(const float* __restrict__ In, const float* __restrict__ O,
                  const float* __restrict__ gw, const float* __restrict__ gb,
                  const float* __restrict__ sp,
                  float* __restrict__ delta, float* __restrict__ seq)
{
    __shared__ float red[256];
    const int r = blockIdx.x;
    const long long base = (long long)r * DD;
    const int tid = threadIdx.x;

    float dot = 0.f;
    for (int d = tid; d < DD; d += 256) dot += In[base + d] * gw[d];
    red[tid] = dot; __syncthreads();
    for (int o = 128; o > 0; o >>= 1) {
        if (tid < o) red[tid] += red[tid + o];
        __syncthreads();
    }
    const float gate = 1.f / (1.f + expf(-(red[0] + gb[0])));
    const float s = sp[0];
    float coef = (s > 20.f) ? s : log1pf(expf(s));
    coef *= gate;

    for (int d = tid; d < DD; d += 256) {
        const float v = coef * (O[base + d] - In[base + d]);
        delta[base + d] = tf32r(v);
        seq[base + d] = v;
    }
}

// ---------------------------------------------------------------------------
// Parallel combine for chambers 1..6 (blockIdx.y = ch-1): delta_ch = round(v)
// ---------------------------------------------------------------------------
__global__ void __launch_bounds__(256)
combine_par6_kernel(const float* __restrict__ hIn, const float* __restrict__ o6,
                    const float* __restrict__ gw, const float* __restrict__ gb,
                    const float* __restrict__ sp, float* __restrict__ delta6)
{
    __shared__ float red[256];
    const int i  = blockIdx.y;          // 0..5 -> chamber i+1
    const int r  = blockIdx.x;
    const long long base  = (long long)r * DD;
    const long long cbase = (long long)i * BT * DD + base;
    const int tid = threadIdx.x;
    const float* gwi = gw + (size_t)(i + 1) * DD;

    float dot = 0.f;
    for (int d = tid; d < DD; d += 256) dot += hIn[base + d] * gwi[d];
    red[tid] = dot; __syncthreads();
    for (int o = 128; o > 0; o >>= 1) {
        if (tid < o) red[tid] += red[tid + o];
        __syncthreads();
    }
    const float gate = 1.f / (1.f + expf(-(red[0] + gb[i + 1])));
    const float s = sp[i + 1];
    float coef = (s > 20.f) ? s : log1pf(expf(s));
    coef *= gate;

    for (int d = tid; d < DD; d += 256)
        delta6[cbase + d] = tf32r(coef * (o6[cbase + d] - hIn[base + d]));
}

// ---------------------------------------------------------------------------
// Sequential combine: seq += softplus(sp)*sigmoid(In.gw+gb)*(O-In)
// ---------------------------------------------------------------------------
__global__ void __launch_bounds__(256)
combine_seq_kernel(const float* __restrict__ In, const float* __restrict__ O,
                   const float* __restrict__ gw, const float* __restrict__ gb,
                   const float* __restrict__ sp, float* __restrict__ seq)
{
    __shared__ float red[256];
    const int r = blockIdx.x;
    const long long base = (long long)r * DD;
    const int tid = threadIdx.x;

    float dot = 0.f;
    for (int d = tid; d < DD; d += 256) dot += In[base + d] * gw[d];
    red[tid] = dot; __syncthreads();
    for (int o = 128; o > 0; o >>= 1) {
        if (tid < o) red[tid] += red[tid + o];
        __syncthreads();
    }
    const float gate = 1.f / (1.f + expf(-(red[0] + gb[0])));
    const float s = sp[0];
    float coef = (s > 20.f) ? s : log1pf(expf(s));
    coef *= gate;

    for (int d = tid; d < DD; d += 256)
        seq[base + d] += coef * (O[base + d] - In[base + d]);
}

// ---------------------------------------------------------------------------
// c = round_tf32(a + b)
// ---------------------------------------------------------------------------
__global__ void add_round_kernel(const float* __restrict__ a,
                                 const float* __restrict__ b,
                                 float* __restrict__ c, int n4)
{
    int i = blockIdx.x * 256 + threadIdx.x;
    if (i < n4) {
        float4 va = reinterpret_cast<const float4*>(a)[i];
        float4 vb = reinterpret_cast<const float4*>(b)[i];
        va.x = tf32r(va.x + vb.x);
        va.y = tf32r(va.y + vb.y);
        va.z = tf32r(va.z + vb.z);
        va.w = tf32r(va.w + vb.w);
        reinterpret_cast<float4*>(c)[i] = va;
    }
}

// ---------------------------------------------------------------------------
// LayerNorm (per row of D=768), output TF32-rounded (feeds GEMMs)
// ---------------------------------------------------------------------------
__global__ void __launch_bounds__(256)
ln_kernel(const float* __restrict__ x, const float* __restrict__ g,
          const float* __restrict__ b, float* __restrict__ out)
{
    __shared__ float r1[256], r2[256];
    const int r = blockIdx.x;
    const long long base = (long long)r * DD;
    const int tid = threadIdx.x;

    float s = 0.f, s2 = 0.f;
    for (int d = tid; d < DD; d += 256) {
        float v = x[base + d];
        s += v; s2 += v * v;
    }
    r1[tid] = s; r2[tid] = s2; __syncthreads();
    for (int o = 128; o > 0; o >>= 1) {
        if (tid < o) { r1[tid] += r1[tid + o]; r2[tid] += r2[tid + o]; }
        __syncthreads();
    }
    const float m   = r1[0] / DD;
    const float var = r2[0] / DD - m * m;
    const float inv = rsqrtf(var + 1e-5f);
    for (int d = tid; d < DD; d += 256)
        out[base + d] = tf32r((x[base + d] - m) * inv * g[d] + b[d]);
}

// ---------------------------------------------------------------------------
__global__ void __launch_bounds__(256)
final_kernel(const float* __restrict__ x, const float* __restrict__ seq,
             const float* __restrict__ par, const float* __restrict__ g,
             const float* __restrict__ b, const float* __restrict__ mode_logit,
             const float* __restrict__ res_gate, float* __restrict__ out)
{
    __shared__ float r1[256], r2[256];
    const int r = blockIdx.x;
    const long long base = (long long)r * DD;
    const int tid = threadIdx.x;

    const float mg = 1.f / (1.f + expf(-mode_logit[0]));
    const float rg = res_gate[0];

    float s = 0.f, s2 = 0.f;
    for (int d = tid; d < DD; d += 256) {
        float e = (1.f - mg) * seq[base + d] + mg * par[base + d];
        s += e; s2 += e * e;
    }
    r1[tid] = s; r2[tid] = s2; __syncthreads();
    for (int o = 128; o > 0; o >>= 1) {
        if (tid < o) { r1[tid] += r1[tid + o]; r2[tid] += r2[tid + o]; }
        __syncthreads();
    }
    const float m   = r1[0] / DD;
    const float var = r2[0] / DD - m * m;
    const float inv = rsqrtf(var + 1e-5f);
    for (int d = tid; d < DD; d += 256) {
        float e  = (1.f - mg) * seq[base + d] + mg * par[base + d];
        float ln = (e - m) * inv * g[d] + b[d];
        out[base + d] = x[base + d] + rg * ln;
    }
}

// ---------------------------------------------------------------------------
extern "C" void kernel_launch(void* const* d_in, const int* in_sizes, int n_in,
                              void* d_out, int out_size)
{
    const float* x             = (const float*)d_in[0];
    const float* Wq            = (const float*)d_in[1];
    const float* Wk            = (const float*)d_in[2];
    const float* gate_w        = (const float*)d_in[3];
    const float* gate_b        = (const float*)d_in[4];
    const float* scale_p       = (const float*)d_in[5];
    const float* merge_W       = (const float*)d_in[6];
    const float* mode_logit    = (const float*)d_in[7];
    const float* residual_gate = (const float*)d_in[8];
    const float* ln_pre_g      = (const float*)d_in[9];
    const float* ln_pre_b      = (const float*)d_in[10];
    const float* ln_post_g     = (const float*)d_in[11];
    const float* ln_post_b     = (const float*)d_in[12];
    float* out = (float*)d_out;

    float *h, *inb, *seq, *par, *q, *k, *o, *dl, *S;
    float *q2, *k2, *o2, *S2, *wq, *wk, *mw;
    cudaGetSymbolAddress((void**)&h,   g_h);
    cudaGetSymbolAddress((void**)&inb, g_in);
    cudaGetSymbolAddress((void**)&seq, g_seq);
    cudaGetSymbolAddress((void**)&par, g_par);
    cudaGetSymbolAddress((void**)&q,   g_q);
    cudaGetSymbolAddress((void**)&k,   g_k);
    cudaGetSymbolAddress((void**)&o,   g_o);
    cudaGetSymbolAddress((void**)&dl,  g_d);
    cudaGetSymbolAddress((void**)&S,   g_S);
    cudaGetSymbolAddress((void**)&q2,  g_q2);
    cudaGetSymbolAddress((void**)&k2,  g_k2);
    cudaGetSymbolAddress((void**)&o2,  g_o2);
    cudaGetSymbolAddress((void**)&S2,  g_S2);
    cudaGetSymbolAddress((void**)&wq,  g_wq);
    cudaGetSymbolAddress((void**)&wk,  g_wk);
    cudaGetSymbolAddress((void**)&mw,  g_mw);

    // Lazily create fork/join resources (host resources, not device memory;
    // created on the first call, reused on the capture call and replays).
    static cudaStream_t s1 = nullptr;
    static cudaEvent_t evF1 = nullptr, evF2 = nullptr, evJ = nullptr;
    if (!s1) {
        cudaStreamCreateWithFlags(&s1, cudaStreamNonBlocking);
        cudaEventCreateWithFlags(&evF1, cudaEventDisableTiming);
        cudaEventCreateWithFlags(&evF2, cudaEventDisableTiming);
        cudaEventCreateWithFlags(&evJ,  cudaEventDisableTiming);
    }

    const float isd = 1.f / sqrtf((float)DD);
    const long long sQK  = (long long)DD * DD;
    const long long sRow = (long long)BT * DD;
    const long long sBT  = (long long)TT * DD;
    const long long sS   = (long long)TT * TT;
    const int wn4 = NCH * DD * DD / 4;

    // -------- weight rounding + pre-LN (stream 0) --------------------------
    round_tf32_kernel<<<(wn4 + 255) / 256, 256>>>(Wq, wq, wn4);
    round_tf32_kernel<<<(wn4 + 255) / 256, 256>>>(Wk, wk, wn4);
    round_tf32_kernel<<<(wn4 + 255) / 256, 256>>>(merge_W, mw, wn4);
    ln_kernel<<<BT, 256>>>(x, ln_pre_g, ln_pre_b, h);

    // -------- fork: s1 runs parallel chambers 1..6 -------------------------
    cudaEventRecord(evF1, 0);
    cudaStreamWaitEvent(s1, evF1, 0);

    mma_gemm<false, false, false, false><<<dim3(6, 32, 6), 256, 0, s1>>>(
        h, DD, 0, wq + sQK, DD, sQK, 0, q + sRow, DD, sRow, BT, DD, DD, 1.f, 0, 0);
    mma_gemm<false, false, false, false><<<dim3(6, 32, 6), 256, 0, s1>>>(
        h, DD, 0, wk + sQK, DD, sQK, 0, k + sRow, DD, sRow, BT, DD, DD, 1.f, 0, 0);
    mma_gemm<true, false, true, false><<<dim3(8, 8, 24), 256, 0, s1>>>(
        q + sRow, DD, sBT, k + sRow, DD, sBT, 0, S, TT, sS, TT, TT, DD, isd, 0, 0);
    softmax_causal_kernel<<<24 * TT, 256, 0, s1>>>(S);
    mma_gemm<false, false, false, true><<<dim3(6, 8, 24), 256, 0, s1>>>(
        S, TT, sS, h, DD, sBT, BB, o + sRow, DD, sBT, TT, DD, TT, 1.f, 0, 0);
    combine_par6_kernel<<<dim3(BT, 6), 256, 0, s1>>>(
        h, o + sRow, gate_w, gate_b, scale_p, dl + sRow);

    // -------- chamber 0 on stream 0 (needed by both branches) --------------
    mma_gemm<false, false, false, false><<<dim3(6, 32, 1), 256>>>(
        h, DD, 0, wq, DD, 0, 0, q2, DD, 0, BT, DD, DD, 1.f, 0, 0);
    mma_gemm<false, false, false, false><<<dim3(6, 32, 1), 256>>>(
        h, DD, 0, wk, DD, 0, 0, k2, DD, 0, BT, DD, DD, 1.f, 0, 0);
    mma_gemm<true, false, true, false><<<dim3(8, 8, BB), 256>>>(
        q2, DD, sBT, k2, DD, sBT, 0, S2, TT, sS, TT, TT, DD, isd, 0, 0);
    softmax_causal_kernel<<<BB * TT, 256>>>(S2);
    mma_gemm<false, false, false, true><<<dim3(6, 8, BB), 256>>>(
        S2, TT, sS, h, DD, sBT, 0, o2, DD, sBT, TT, DD, TT, 1.f, 0, 0);
    combine_c0_kernel<<<BT, 256>>>(h, o2, gate_w, gate_b, scale_p, dl, seq);

    // delta_0 ready -> merge GEMM on s1 (single K=7*768 GEMM, A chunked)
    cudaEventRecord(evF2, 0);
    cudaStreamWaitEvent(s1, evF2, 0);
    mma_gemm<true, false, false, false><<<dim3(6, 32, 1), 256, 0, s1>>>(
        dl, DD, 0, mw, NCH * DD, 0, 0, par, DD, 0,
        BT, DD, NCH * DD, 1.f, DD, sRow);
    cudaEventRecord(evJ, s1);

    // -------- sequential chambers 1..6 on stream 0 -------------------------
    const int n4 = BT * DD / 4;
    for (int i = 1; i < NCH; i++) {
        add_round_kernel<<<(n4 + 255) / 256, 256>>>(h, seq, inb, n4);
        mma_gemm<false, false, false, false><<<dim3(6, 32, 1), 256>>>(
            inb, DD, 0, wq + (size_t)i * sQK, DD, 0, 0,
            q2, DD, 0, BT, DD, DD, 1.f, 0, 0);
        mma_gemm<false, false, false, false><<<dim3(6, 32, 1), 256>>>(
            inb, DD, 0, wk + (size_t)i * sQK, DD, 0, 0,
            k2, DD, 0, BT, DD, DD, 1.f, 0, 0);
        mma_gemm<true, false, true, false><<<dim3(8, 8, BB), 256>>>(
            q2, DD, sBT, k2, DD, sBT, 0, S2, TT, sS, TT, TT, DD, isd, 0, 0);
        softmax_causal_kernel<<<BB * TT, 256>>>(S2);
        mma_gemm<false, false, false, true><<<dim3(6, 8, BB), 256>>>(
            S2, TT, sS, inb, DD, sBT, 0, o2, DD, sBT, TT, DD, TT, 1.f, 0, 0);
        combine_seq_kernel<<<BT, 256>>>(inb, o2, gate_w + (size_t)i * DD,
                                        gate_b + i, scale_p + i, seq);
    }

    // -------- join + finalize ----------------------------------------------
    cudaStreamWaitEvent(0, evJ, 0);
    final_kernel<<<BT, 256>>>(x, seq, par, ln_post_g, ln_post_b,
                              mode_logit, residual_gate, out);
}